// round 2
// baseline (speedup 1.0000x reference)
#include <cuda_runtime.h>
#include <math.h>

#define B_   4
#define T_   2048
#define C_   1024
#define HQ_  16
#define HKV_ 4
#define D_   64
#define G_   4
#define N_   (B_*T_)        // 8192 rows
#define KVC_ (HKV_*D_)      // 256

// ---------------- scratch (no allocations allowed) ----------------
__device__ float g_Q[(size_t)N_*C_];     // [B*T, 1024] col = hq*64+d
__device__ float g_K[(size_t)N_*KVC_];   // [B*T, 256]  col = h*64+d
__device__ float g_V[(size_t)N_*KVC_];
__device__ float g_Y[(size_t)N_*C_];     // pre-Wo attention output
__device__ float g_M[B_*HQ_*T_];         // row max per (b,hq,t)
__device__ float g_L[B_*HQ_*T_];         // row sumexp

// ---------------- generic fp32 GEMM: C = A[M,K]@B[K,N] + bias ----------------
// 128x128 tile, k-step 8, 256 threads, 8x8 per thread.
__global__ __launch_bounds__(256) void gemm_bias_kernel(
    const float* __restrict__ A, const float* __restrict__ Bm,
    const float* __restrict__ bias, float* __restrict__ Cm,
    int M, int N, int K)
{
    __shared__ float As[8][128];   // As[kk][row]
    __shared__ float Bs[8][128];   // Bs[kk][col]
    const int tid = threadIdx.x;
    const int tx = tid & 15, ty = tid >> 4;
    const int row0 = blockIdx.y * 128, col0 = blockIdx.x * 128;

    float acc[8][8];
#pragma unroll
    for (int i = 0; i < 8; i++)
#pragma unroll
        for (int j = 0; j < 8; j++) acc[i][j] = 0.f;

    for (int k0 = 0; k0 < K; k0 += 8) {
        // load A tile 128x8 (transposed into smem)
        {
            int r  = tid >> 1;
            int kq = (tid & 1) * 4;
            float4 a4 = *(const float4*)&A[(size_t)(row0 + r) * K + k0 + kq];
            As[kq + 0][r] = a4.x; As[kq + 1][r] = a4.y;
            As[kq + 2][r] = a4.z; As[kq + 3][r] = a4.w;
        }
        // load B tile 8x128
        {
            int c  = tid & 127;
            int kk = tid >> 7;
#pragma unroll
            for (int p = 0; p < 4; p++)
                Bs[kk + 2 * p][c] = Bm[(size_t)(k0 + kk + 2 * p) * N + col0 + c];
        }
        __syncthreads();
#pragma unroll
        for (int kk = 0; kk < 8; kk++) {
            float a[8], b[8];
            *(float4*)&a[0] = *(const float4*)&As[kk][ty * 8];
            *(float4*)&a[4] = *(const float4*)&As[kk][ty * 8 + 4];
            *(float4*)&b[0] = *(const float4*)&Bs[kk][tx * 8];
            *(float4*)&b[4] = *(const float4*)&Bs[kk][tx * 8 + 4];
#pragma unroll
            for (int i = 0; i < 8; i++)
#pragma unroll
                for (int j = 0; j < 8; j++) acc[i][j] += a[i] * b[j];
        }
        __syncthreads();
    }
    // epilogue with bias
    float4 b0 = *(const float4*)&bias[col0 + tx * 8];
    float4 b1 = *(const float4*)&bias[col0 + tx * 8 + 4];
#pragma unroll
    for (int i = 0; i < 8; i++) {
        size_t off = (size_t)(row0 + ty * 8 + i) * N + col0 + tx * 8;
        float4 c0 = make_float4(acc[i][0] + b0.x, acc[i][1] + b0.y,
                                acc[i][2] + b0.z, acc[i][3] + b0.w);
        float4 c1 = make_float4(acc[i][4] + b1.x, acc[i][5] + b1.y,
                                acc[i][6] + b1.z, acc[i][7] + b1.w);
        *(float4*)&Cm[off]     = c0;
        *(float4*)&Cm[off + 4] = c1;
    }
}

// ---------------- attention pass 1: row max + sumexp (flash stats) ----------------
// grid: (T/64, B*HQ), 256 threads, 64x64 score tiles, 4x4 frag per thread.
__global__ __launch_bounds__(256) void attn_stats_kernel()
{
    __shared__ float Qs[64][64];   // swizzled: Qs[d][r ^ (d&31)]
    __shared__ float Ks[64][64];   // swizzled: Ks[d][kc ^ (d&31)]
    const int tid = threadIdx.x;
    const int tx = tid & 15, ty = tid >> 4;
    const int tx4 = tx * 4, ty4 = ty * 4;
    const int bh = blockIdx.y;
    const int b  = bh >> 4;         // /HQ
    const int hq = bh & 15;
    const int h  = hq >> 2;         // /G
    const int q0 = blockIdx.x * 64;

    // load Q tile (transposed+swizzled)
    for (int idx = tid; idx < 4096; idx += 256) {
        int r = idx >> 6, d = idx & 63;
        Qs[d][r ^ (d & 31)] = g_Q[(size_t)(b * T_ + q0 + r) * C_ + hq * D_ + d];
    }

    float runm[4], runs[4];
#pragma unroll
    for (int i = 0; i < 4; i++) { runm[i] = -1e30f; runs[i] = 0.f; }

    const int nkt = (q0 >> 6) + 1;
    for (int kt = 0; kt < nkt; kt++) {
        const int k0 = kt * 64;
        for (int idx = tid; idx < 4096; idx += 256) {
            int r = idx >> 6, d = idx & 63;
            Ks[d][r ^ (d & 31)] = g_K[(size_t)(b * T_ + k0 + r) * KVC_ + h * D_ + d];
        }
        __syncthreads();

        float s[4][4];
#pragma unroll
        for (int i = 0; i < 4; i++)
#pragma unroll
            for (int j = 0; j < 4; j++) s[i][j] = 0.f;

#pragma unroll 4
        for (int d = 0; d < 64; d++) {
            int c = d & 31;
            float a0 = Qs[d][(ty4 + 0) ^ c], a1 = Qs[d][(ty4 + 1) ^ c];
            float a2 = Qs[d][(ty4 + 2) ^ c], a3 = Qs[d][(ty4 + 3) ^ c];
            float b0 = Ks[d][(tx4 + 0) ^ c], b1 = Ks[d][(tx4 + 1) ^ c];
            float b2 = Ks[d][(tx4 + 2) ^ c], b3 = Ks[d][(tx4 + 3) ^ c];
            s[0][0] += a0*b0; s[0][1] += a0*b1; s[0][2] += a0*b2; s[0][3] += a0*b3;
            s[1][0] += a1*b0; s[1][1] += a1*b1; s[1][2] += a1*b2; s[1][3] += a1*b3;
            s[2][0] += a2*b0; s[2][1] += a2*b1; s[2][2] += a2*b2; s[2][3] += a2*b3;
            s[3][0] += a3*b0; s[3][1] += a3*b1; s[3][2] += a3*b2; s[3][3] += a3*b3;
        }
#pragma unroll
        for (int i = 0; i < 4; i++)
#pragma unroll
            for (int j = 0; j < 4; j++) s[i][j] *= 0.125f;

        if (k0 == q0) {   // diagonal tile: causal mask
#pragma unroll
            for (int i = 0; i < 4; i++)
#pragma unroll
                for (int j = 0; j < 4; j++)
                    if (k0 + tx4 + j > q0 + ty4 + i) s[i][j] = -1e30f;
        }

#pragma unroll
        for (int i = 0; i < 4; i++) {
            float m = fmaxf(fmaxf(s[i][0], s[i][1]), fmaxf(s[i][2], s[i][3]));
#pragma unroll
            for (int off = 8; off > 0; off >>= 1)
                m = fmaxf(m, __shfl_xor_sync(0xffffffffu, m, off));
            float nm = fmaxf(runm[i], m);
            float sm = __expf(s[i][0] - nm) + __expf(s[i][1] - nm)
                     + __expf(s[i][2] - nm) + __expf(s[i][3] - nm);
#pragma unroll
            for (int off = 8; off > 0; off >>= 1)
                sm += __shfl_xor_sync(0xffffffffu, sm, off);
            runs[i] = runs[i] * __expf(runm[i] - nm) + sm;
            runm[i] = nm;
        }
        __syncthreads();
    }

    if (tx == 0) {
#pragma unroll
        for (int i = 0; i < 4; i++) {
            g_M[bh * T_ + q0 + ty4 + i] = runm[i];
            g_L[bh * T_ + q0 + ty4 + i] = runs[i];
        }
    }
}

// ---------------- attention pass 2: normalize, write att, accumulate Y ----------------
__global__ __launch_bounds__(256) void attn_finalize_kernel(float* __restrict__ att,
                                                            int write_att)
{
    __shared__ float Qs[64][64];    // swizzled
    __shared__ float KPs[64][64];   // K (swizzled) then reused as P (natural row-major)
    __shared__ float Vs[64][64];    // natural [k][d]
    float* Ps = &KPs[0][0];

    const int tid = threadIdx.x;
    const int tx = tid & 15, ty = tid >> 4;
    const int tx4 = tx * 4, ty4 = ty * 4;
    const int bh = blockIdx.y;
    const int b  = bh >> 4;
    const int hq = bh & 15;
    const int h  = hq >> 2;
    const int g  = hq & 3;
    const int q0 = blockIdx.x * 64;
    const size_t attbase = (size_t)((b * G_ + g) * HKV_ + h) * T_ * T_;

    for (int idx = tid; idx < 4096; idx += 256) {
        int r = idx >> 6, d = idx & 63;
        Qs[d][r ^ (d & 31)] = g_Q[(size_t)(b * T_ + q0 + r) * C_ + hq * D_ + d];
    }

    float mrow[4], rinv[4];
#pragma unroll
    for (int i = 0; i < 4; i++) {
        mrow[i] = g_M[bh * T_ + q0 + ty4 + i];
        rinv[i] = 1.f / g_L[bh * T_ + q0 + ty4 + i];
    }

    float yacc[4][4];
#pragma unroll
    for (int i = 0; i < 4; i++)
#pragma unroll
        for (int j = 0; j < 4; j++) yacc[i][j] = 0.f;

    const int diag = q0 >> 6;
    for (int kt = 0; kt < T_ / 64; kt++) {
        const int k0 = kt * 64;
        if (kt > diag) {            // fully masked: att weights are exactly 0
            if (write_att) {
                float4 z = make_float4(0.f, 0.f, 0.f, 0.f);
#pragma unroll
                for (int i = 0; i < 4; i++)
                    *(float4*)&att[attbase + (size_t)(q0 + ty4 + i) * T_ + k0 + tx4] = z;
            }
            continue;
        }
        for (int idx = tid; idx < 4096; idx += 256) {
            int r = idx >> 6, d = idx & 63;
            KPs[d][r ^ (d & 31)] = g_K[(size_t)(b * T_ + k0 + r) * KVC_ + h * D_ + d];
            Vs[r][d]             = g_V[(size_t)(b * T_ + k0 + r) * KVC_ + h * D_ + d];
        }
        __syncthreads();

        float s[4][4];
#pragma unroll
        for (int i = 0; i < 4; i++)
#pragma unroll
            for (int j = 0; j < 4; j++) s[i][j] = 0.f;
#pragma unroll 4
        for (int d = 0; d < 64; d++) {
            int c = d & 31;
            float a0 = Qs[d][(ty4 + 0) ^ c], a1 = Qs[d][(ty4 + 1) ^ c];
            float a2 = Qs[d][(ty4 + 2) ^ c], a3 = Qs[d][(ty4 + 3) ^ c];
            float b0 = KPs[d][(tx4 + 0) ^ c], b1 = KPs[d][(tx4 + 1) ^ c];
            float b2 = KPs[d][(tx4 + 2) ^ c], b3 = KPs[d][(tx4 + 3) ^ c];
            s[0][0] += a0*b0; s[0][1] += a0*b1; s[0][2] += a0*b2; s[0][3] += a0*b3;
            s[1][0] += a1*b0; s[1][1] += a1*b1; s[1][2] += a1*b2; s[1][3] += a1*b3;
            s[2][0] += a2*b0; s[2][1] += a2*b1; s[2][2] += a2*b2; s[2][3] += a2*b3;
            s[3][0] += a3*b0; s[3][1] += a3*b1; s[3][2] += a3*b2; s[3][3] += a3*b3;
        }

        float p[4][4];
#pragma unroll
        for (int i = 0; i < 4; i++)
#pragma unroll
            for (int j = 0; j < 4; j++) {
                float sv = s[i][j] * 0.125f;
                if (kt == diag && (k0 + tx4 + j > q0 + ty4 + i)) sv = -1e30f;
                p[i][j] = __expf(sv - mrow[i]) * rinv[i];
            }

        __syncthreads();   // all K reads done before overwriting KPs as P
#pragma unroll
        for (int i = 0; i < 4; i++) {
            float4 p4 = make_float4(p[i][0], p[i][1], p[i][2], p[i][3]);
            *(float4*)&Ps[(ty4 + i) * 64 + tx4] = p4;
            if (write_att)
                *(float4*)&att[attbase + (size_t)(q0 + ty4 + i) * T_ + k0 + tx4] = p4;
        }
        __syncthreads();

#pragma unroll 4
        for (int kc = 0; kc < 64; kc++) {
            float a0 = Ps[(ty4 + 0) * 64 + kc], a1 = Ps[(ty4 + 1) * 64 + kc];
            float a2 = Ps[(ty4 + 2) * 64 + kc], a3 = Ps[(ty4 + 3) * 64 + kc];
            float b0 = Vs[kc][tx4 + 0], b1 = Vs[kc][tx4 + 1];
            float b2 = Vs[kc][tx4 + 2], b3 = Vs[kc][tx4 + 3];
            yacc[0][0] += a0*b0; yacc[0][1] += a0*b1; yacc[0][2] += a0*b2; yacc[0][3] += a0*b3;
            yacc[1][0] += a1*b0; yacc[1][1] += a1*b1; yacc[1][2] += a1*b2; yacc[1][3] += a1*b3;
            yacc[2][0] += a2*b0; yacc[2][1] += a2*b1; yacc[2][2] += a2*b2; yacc[2][3] += a2*b3;
            yacc[3][0] += a3*b0; yacc[3][1] += a3*b1; yacc[3][2] += a3*b2; yacc[3][3] += a3*b3;
        }
        __syncthreads();
    }

#pragma unroll
    for (int i = 0; i < 4; i++) {
        float4 y4 = make_float4(yacc[i][0], yacc[i][1], yacc[i][2], yacc[i][3]);
        *(float4*)&g_Y[(size_t)(b * T_ + q0 + ty4 + i) * C_ + hq * D_ + tx4] = y4;
    }
}

// ---------------- launch ----------------
extern "C" void kernel_launch(void* const* d_in, const int* in_sizes, int n_in,
                              void* d_out, int out_size)
{
    const float* x  = (const float*)d_in[0];
    const float* Wq = (const float*)d_in[1];
    const float* bq = (const float*)d_in[2];
    const float* Wk = (const float*)d_in[3];
    const float* bk = (const float*)d_in[4];
    const float* Wv = (const float*)d_in[5];
    const float* bv = (const float*)d_in[6];
    const float* Wo = (const float*)d_in[7];
    const float* bo = (const float*)d_in[8];

    // Resolve scratch addresses once (first call is the uncaptured correctness
    // run, so these runtime queries never occur inside graph capture).
    static float *qp = nullptr, *kp = nullptr, *vp = nullptr, *yp = nullptr;
    if (!qp) {
        cudaGetSymbolAddress((void**)&qp, g_Q);
        cudaGetSymbolAddress((void**)&kp, g_K);
        cudaGetSymbolAddress((void**)&vp, g_V);
        cudaGetSymbolAddress((void**)&yp, g_Y);
    }

    const size_t yElems   = (size_t)N_ * C_;                       // 8,388,608
    const size_t attElems = (size_t)B_ * G_ * HKV_ * T_ * T_;      // 268,435,456
    float* out = (float*)d_out;
    float* yOut;
    float* attOut;
    int    writeAtt;
    size_t osz = (size_t)out_size;
    if (osz >= yElems + attElems)      { yOut = out; attOut = out + yElems; writeAtt = 1; }
    else if (osz == attElems)          { yOut = qp;  attOut = out;          writeAtt = 1; }
    else                               { yOut = out; attOut = qp;           writeAtt = 0; }

    dim3 blk(256);
    gemm_bias_kernel<<<dim3(C_   / 128, N_ / 128), blk>>>(x, Wq, bq, qp, N_, C_,   C_);
    gemm_bias_kernel<<<dim3(KVC_ / 128, N_ / 128), blk>>>(x, Wk, bk, kp, N_, KVC_, C_);
    gemm_bias_kernel<<<dim3(KVC_ / 128, N_ / 128), blk>>>(x, Wv, bv, vp, N_, KVC_, C_);
    attn_stats_kernel   <<<dim3(T_ / 64, B_ * HQ_), blk>>>();
    attn_finalize_kernel<<<dim3(T_ / 64, B_ * HQ_), blk>>>(attOut, writeAtt);
    gemm_bias_kernel<<<dim3(C_ / 128, N_ / 128), blk>>>(yp, Wo, bo, yOut, N_, C_, C_);
}

// round 4
// speedup vs baseline: 1.8629x; 1.8629x over previous
// R4 = R3 resubmitted unchanged: R3 hit a broker-side "container failed twice"
// (same signature as R1, which passed on identical resubmission in R2).
#include <cuda_runtime.h>
#include <math.h>
#include <stdint.h>

#define B_   4
#define T_   2048
#define C_   1024
#define HQ_  16
#define HKV_ 4
#define D_   64
#define G_   4
#define N_   (B_*T_)        // 8192 rows
#define KVC_ (HKV_*D_)      // 256
#define PAD  68             // padded row stride (floats) for conflict-free mma frag loads

// ---------------- scratch (no allocations allowed) ----------------
__device__ float g_Q[(size_t)N_*C_];     // [B*T, 1024] col = hq*64+d
__device__ float g_K[(size_t)N_*KVC_];   // [B*T, 256]  col = h*64+d
__device__ float g_V[(size_t)N_*KVC_];
__device__ float g_Y[(size_t)N_*C_];     // pre-Wo attention output
__device__ float g_M[B_*HQ_*T_];         // row max per (b,hq,t)
__device__ float g_L[B_*HQ_*T_];         // row sumexp

// ---------------- tf32 mma helpers ----------------
__device__ __forceinline__ void mma_tf32(float c[4],
    uint32_t a0, uint32_t a1, uint32_t a2, uint32_t a3,
    uint32_t b0, uint32_t b1)
{
    asm volatile(
        "mma.sync.aligned.m16n8k8.row.col.f32.tf32.tf32.f32 "
        "{%0,%1,%2,%3}, {%4,%5,%6,%7}, {%8,%9}, {%0,%1,%2,%3};\n"
        : "+f"(c[0]), "+f"(c[1]), "+f"(c[2]), "+f"(c[3])
        : "r"(a0), "r"(a1), "r"(a2), "r"(a3), "r"(b0), "r"(b1));
}

// round-to-nearest f32 -> tf32 (kills RZ truncation bias in the mma inputs)
__device__ __forceinline__ float tf32rn(float x)
{
    uint32_t u;
    asm("cvt.rna.tf32.f32 %0, %1;" : "=r"(u) : "f"(x));
    return __uint_as_float(u);
}

// ---------------- generic fp32 GEMM: C = A[M,K]@B[K,N] + bias ----------------
// 128x128 tile, k-step 8, 256 threads, 8x8 per thread.
__global__ __launch_bounds__(256) void gemm_bias_kernel(
    const float* __restrict__ A, const float* __restrict__ Bm,
    const float* __restrict__ bias, float* __restrict__ Cm,
    int M, int N, int K)
{
    __shared__ float As[8][128];
    __shared__ float Bs[8][128];
    const int tid = threadIdx.x;
    const int tx = tid & 15, ty = tid >> 4;
    const int row0 = blockIdx.y * 128, col0 = blockIdx.x * 128;

    float acc[8][8];
#pragma unroll
    for (int i = 0; i < 8; i++)
#pragma unroll
        for (int j = 0; j < 8; j++) acc[i][j] = 0.f;

    for (int k0 = 0; k0 < K; k0 += 8) {
        {
            int r  = tid >> 1;
            int kq = (tid & 1) * 4;
            float4 a4 = *(const float4*)&A[(size_t)(row0 + r) * K + k0 + kq];
            As[kq + 0][r] = a4.x; As[kq + 1][r] = a4.y;
            As[kq + 2][r] = a4.z; As[kq + 3][r] = a4.w;
        }
        {
            int c  = tid & 127;
            int kk = tid >> 7;
#pragma unroll
            for (int p = 0; p < 4; p++)
                Bs[kk + 2 * p][c] = Bm[(size_t)(k0 + kk + 2 * p) * N + col0 + c];
        }
        __syncthreads();
#pragma unroll
        for (int kk = 0; kk < 8; kk++) {
            float a[8], b[8];
            *(float4*)&a[0] = *(const float4*)&As[kk][ty * 8];
            *(float4*)&a[4] = *(const float4*)&As[kk][ty * 8 + 4];
            *(float4*)&b[0] = *(const float4*)&Bs[kk][tx * 8];
            *(float4*)&b[4] = *(const float4*)&Bs[kk][tx * 8 + 4];
#pragma unroll
            for (int i = 0; i < 8; i++)
#pragma unroll
                for (int j = 0; j < 8; j++) acc[i][j] += a[i] * b[j];
        }
        __syncthreads();
    }
    float4 b0 = *(const float4*)&bias[col0 + tx * 8];
    float4 b1 = *(const float4*)&bias[col0 + tx * 8 + 4];
#pragma unroll
    for (int i = 0; i < 8; i++) {
        size_t off = (size_t)(row0 + ty * 8 + i) * N + col0 + tx * 8;
        float4 c0 = make_float4(acc[i][0] + b0.x, acc[i][1] + b0.y,
                                acc[i][2] + b0.z, acc[i][3] + b0.w);
        float4 c1 = make_float4(acc[i][4] + b1.x, acc[i][5] + b1.y,
                                acc[i][6] + b1.z, acc[i][7] + b1.w);
        *(float4*)&Cm[off]     = c0;
        *(float4*)&Cm[off + 4] = c1;
    }
}

// ---------------- attention pass 1 (mma): row max + sumexp ----------------
// block: 256 thr = 8 warps. warp = (mstrip = w&3: 16 q-rows) x (nhalf = w>>2: 32 k-cols).
// Each warp keeps running (m,l) over ITS columns; halves combined at the end.
__global__ __launch_bounds__(256) void attn_stats_mma()
{
    __shared__ float Qs[64 * PAD];
    __shared__ float Ks[64 * PAD];
    __shared__ float redM[2][64];
    __shared__ float redL[2][64];

    const int tid  = threadIdx.x;
    const int w    = tid >> 5;
    const int lane = tid & 31;
    const int gid  = lane >> 2;   // 0..7
    const int tig  = lane & 3;    // 0..3
    const int mstrip = w & 3;
    const int nhalf  = w >> 2;
    const int row0  = mstrip * 16 + gid;   // + 8 for second row
    const int nbase = nhalf * 32;

    const int bh = blockIdx.y;
    const int b  = bh >> 4, hq = bh & 15, h = hq >> 2;
    const int q0 = blockIdx.x * 64;

    // load Q tile [64 rows][64 d], natural layout, tf32-rounded
    {
        const float* src = &g_Q[(size_t)(b * T_ + q0) * C_ + hq * D_];
        for (int idx = tid; idx < 1024; idx += 256) {
            int r = idx >> 4, d = (idx & 15) << 2;
            float4 v = *(const float4*)&src[(size_t)r * C_ + d];
            v.x = tf32rn(v.x); v.y = tf32rn(v.y); v.z = tf32rn(v.z); v.w = tf32rn(v.w);
            *(float4*)&Qs[r * PAD + d] = v;
        }
    }

    float runm0 = -1e30f, runs0 = 0.f, runm1 = -1e30f, runs1 = 0.f;
    const int diag = q0 >> 6;

    for (int kt = 0; kt <= diag; kt++) {
        const int k0 = kt * 64;
        const float* ksrc = &g_K[(size_t)(b * T_ + k0) * KVC_ + h * D_];
        for (int idx = tid; idx < 1024; idx += 256) {
            int r = idx >> 4, d = (idx & 15) << 2;
            float4 v = *(const float4*)&ksrc[(size_t)r * KVC_ + d];
            v.x = tf32rn(v.x); v.y = tf32rn(v.y); v.z = tf32rn(v.z); v.w = tf32rn(v.w);
            *(float4*)&Ks[r * PAD + d] = v;
        }
        __syncthreads();

        float c[4][4];
#pragma unroll
        for (int nt = 0; nt < 4; nt++)
#pragma unroll
            for (int e = 0; e < 4; e++) c[nt][e] = 0.f;

#pragma unroll
        for (int ks2 = 0; ks2 < 8; ks2++) {
            const int d0 = ks2 * 8;
            uint32_t a0 = __float_as_uint(Qs[(row0    ) * PAD + d0 + tig]);
            uint32_t a1 = __float_as_uint(Qs[(row0 + 8) * PAD + d0 + tig]);
            uint32_t a2 = __float_as_uint(Qs[(row0    ) * PAD + d0 + tig + 4]);
            uint32_t a3 = __float_as_uint(Qs[(row0 + 8) * PAD + d0 + tig + 4]);
#pragma unroll
            for (int nt = 0; nt < 4; nt++) {
                const int nc = nbase + nt * 8 + gid;
                uint32_t b0 = __float_as_uint(Ks[nc * PAD + d0 + tig]);
                uint32_t b1 = __float_as_uint(Ks[nc * PAD + d0 + tig + 4]);
                mma_tf32(c[nt], a0, a1, a2, a3, b0, b1);
            }
        }

        // scale 1/sqrt(64) + causal mask on the diagonal tile
        const bool dm = (kt == diag);
#pragma unroll
        for (int nt = 0; nt < 4; nt++) {
            const int colb = k0 + nbase + nt * 8 + 2 * tig;
#pragma unroll
            for (int e = 0; e < 2; e++) {
                float v0 = c[nt][e]     * 0.125f;
                float v1 = c[nt][2 + e] * 0.125f;
                if (dm && colb + e > q0 + row0    ) v0 = -1e30f;
                if (dm && colb + e > q0 + row0 + 8) v1 = -1e30f;
                c[nt][e] = v0; c[nt][2 + e] = v1;
            }
        }

        // per-row online max/sum (rows row0 and row0+8); reduce across the tig quad
        float m0 = c[0][0], m1 = c[0][2];
#pragma unroll
        for (int nt = 0; nt < 4; nt++) {
            m0 = fmaxf(m0, fmaxf(c[nt][0], c[nt][1]));
            m1 = fmaxf(m1, fmaxf(c[nt][2], c[nt][3]));
        }
        m0 = fmaxf(m0, __shfl_xor_sync(0xffffffffu, m0, 1));
        m0 = fmaxf(m0, __shfl_xor_sync(0xffffffffu, m0, 2));
        m1 = fmaxf(m1, __shfl_xor_sync(0xffffffffu, m1, 1));
        m1 = fmaxf(m1, __shfl_xor_sync(0xffffffffu, m1, 2));

        const float nm0 = fmaxf(runm0, m0);
        const float nm1 = fmaxf(runm1, m1);
        float s0 = 0.f, s1 = 0.f;
#pragma unroll
        for (int nt = 0; nt < 4; nt++) {
            s0 += __expf(c[nt][0] - nm0) + __expf(c[nt][1] - nm0);
            s1 += __expf(c[nt][2] - nm1) + __expf(c[nt][3] - nm1);
        }
        s0 += __shfl_xor_sync(0xffffffffu, s0, 1);
        s0 += __shfl_xor_sync(0xffffffffu, s0, 2);
        s1 += __shfl_xor_sync(0xffffffffu, s1, 1);
        s1 += __shfl_xor_sync(0xffffffffu, s1, 2);

        runs0 = runs0 * __expf(runm0 - nm0) + s0;  runm0 = nm0;
        runs1 = runs1 * __expf(runm1 - nm1) + s1;  runm1 = nm1;
        __syncthreads();
    }

    // combine the two column-halves per row
    if (tig == 0) {
        redM[nhalf][row0]     = runm0;  redL[nhalf][row0]     = runs0;
        redM[nhalf][row0 + 8] = runm1;  redL[nhalf][row0 + 8] = runs1;
    }
    __syncthreads();
    if (nhalf == 0 && tig == 0) {
#pragma unroll
        for (int rr = 0; rr < 2; rr++) {
            const int r = row0 + rr * 8;
            const float ma = redM[0][r], mb = redM[1][r];
            const float m  = fmaxf(ma, mb);
            const float l  = redL[0][r] * __expf(ma - m) + redL[1][r] * __expf(mb - m);
            g_M[bh * T_ + q0 + r] = m;
            g_L[bh * T_ + q0 + r] = l;
        }
    }
}

// ---------------- attention pass 2 (mma): P write + Y accumulate ----------------
__global__ __launch_bounds__(256) void attn_finalize_mma(float* __restrict__ att,
                                                         int write_att)
{
    extern __shared__ float smdyn[];
    float* Qs = smdyn;
    float* Ks = smdyn + 64 * PAD;
    float* Vs = smdyn + 2 * 64 * PAD;
    float* Ps = smdyn + 3 * 64 * PAD;

    const int tid  = threadIdx.x;
    const int w    = tid >> 5;
    const int lane = tid & 31;
    const int gid  = lane >> 2;
    const int tig  = lane & 3;
    const int mstrip = w & 3;
    const int nhalf  = w >> 2;
    const int row0  = mstrip * 16 + gid;
    const int nbase = nhalf * 32;

    const int bh = blockIdx.y;
    const int b  = bh >> 4, hq = bh & 15, h = hq >> 2, g = hq & 3;
    const int q0 = blockIdx.x * 64;
    const size_t attbase = (size_t)((b * G_ + g) * HKV_ + h) * T_ * T_;

    {
        const float* src = &g_Q[(size_t)(b * T_ + q0) * C_ + hq * D_];
        for (int idx = tid; idx < 1024; idx += 256) {
            int r = idx >> 4, d = (idx & 15) << 2;
            float4 v = *(const float4*)&src[(size_t)r * C_ + d];
            v.x = tf32rn(v.x); v.y = tf32rn(v.y); v.z = tf32rn(v.z); v.w = tf32rn(v.w);
            *(float4*)&Qs[r * PAD + d] = v;
        }
    }

    const float mr0 = g_M[bh * T_ + q0 + row0];
    const float li0 = 1.f / g_L[bh * T_ + q0 + row0];
    const float mr1 = g_M[bh * T_ + q0 + row0 + 8];
    const float li1 = 1.f / g_L[bh * T_ + q0 + row0 + 8];

    float yc[4][4];
#pragma unroll
    for (int nt = 0; nt < 4; nt++)
#pragma unroll
        for (int e = 0; e < 4; e++) yc[nt][e] = 0.f;

    const int diag = q0 >> 6;
    for (int kt = 0; kt < T_ / 64; kt++) {
        const int k0 = kt * 64;
        if (kt > diag) {                       // fully-masked tile: exact zeros
            if (write_att) {
                const float4 z = make_float4(0.f, 0.f, 0.f, 0.f);
                for (int idx = tid; idx < 1024; idx += 256) {
                    int r = idx >> 4, cc = (idx & 15) << 2;
                    *(float4*)&att[attbase + (size_t)(q0 + r) * T_ + k0 + cc] = z;
                }
            }
            continue;
        }

        {
            const float* ksrc = &g_K[(size_t)(b * T_ + k0) * KVC_ + h * D_];
            const float* vsrc = &g_V[(size_t)(b * T_ + k0) * KVC_ + h * D_];
            for (int idx = tid; idx < 1024; idx += 256) {
                int r = idx >> 4, d = (idx & 15) << 2;
                float4 kv = *(const float4*)&ksrc[(size_t)r * KVC_ + d];
                float4 vv = *(const float4*)&vsrc[(size_t)r * KVC_ + d];
                kv.x = tf32rn(kv.x); kv.y = tf32rn(kv.y); kv.z = tf32rn(kv.z); kv.w = tf32rn(kv.w);
                vv.x = tf32rn(vv.x); vv.y = tf32rn(vv.y); vv.z = tf32rn(vv.z); vv.w = tf32rn(vv.w);
                *(float4*)&Ks[r * PAD + d] = kv;
                *(float4*)&Vs[r * PAD + d] = vv;
            }
        }
        __syncthreads();

        // S = Q K^T
        float c[4][4];
#pragma unroll
        for (int nt = 0; nt < 4; nt++)
#pragma unroll
            for (int e = 0; e < 4; e++) c[nt][e] = 0.f;
#pragma unroll
        for (int ks2 = 0; ks2 < 8; ks2++) {
            const int d0 = ks2 * 8;
            uint32_t a0 = __float_as_uint(Qs[(row0    ) * PAD + d0 + tig]);
            uint32_t a1 = __float_as_uint(Qs[(row0 + 8) * PAD + d0 + tig]);
            uint32_t a2 = __float_as_uint(Qs[(row0    ) * PAD + d0 + tig + 4]);
            uint32_t a3 = __float_as_uint(Qs[(row0 + 8) * PAD + d0 + tig + 4]);
#pragma unroll
            for (int nt = 0; nt < 4; nt++) {
                const int nc = nbase + nt * 8 + gid;
                uint32_t b0 = __float_as_uint(Ks[nc * PAD + d0 + tig]);
                uint32_t b1 = __float_as_uint(Ks[nc * PAD + d0 + tig + 4]);
                mma_tf32(c[nt], a0, a1, a2, a3, b0, b1);
            }
        }

        // softmax-normalize with saved stats, write P (att + smem)
        const bool dm = (kt == diag);
#pragma unroll
        for (int nt = 0; nt < 4; nt++) {
            const int col  = nbase + nt * 8 + 2 * tig;
            const int colg = k0 + col;
            float v00 = c[nt][0] * 0.125f, v01 = c[nt][1] * 0.125f;
            float v10 = c[nt][2] * 0.125f, v11 = c[nt][3] * 0.125f;
            if (dm) {
                if (colg     > q0 + row0    ) v00 = -1e30f;
                if (colg + 1 > q0 + row0    ) v01 = -1e30f;
                if (colg     > q0 + row0 + 8) v10 = -1e30f;
                if (colg + 1 > q0 + row0 + 8) v11 = -1e30f;
            }
            const float p00 = __expf(v00 - mr0) * li0;
            const float p01 = __expf(v01 - mr0) * li0;
            const float p10 = __expf(v10 - mr1) * li1;
            const float p11 = __expf(v11 - mr1) * li1;
            *(float2*)&Ps[(row0    ) * PAD + col] = make_float2(tf32rn(p00), tf32rn(p01));
            *(float2*)&Ps[(row0 + 8) * PAD + col] = make_float2(tf32rn(p10), tf32rn(p11));
            if (write_att) {
                *(float2*)&att[attbase + (size_t)(q0 + row0    ) * T_ + colg] = make_float2(p00, p01);
                *(float2*)&att[attbase + (size_t)(q0 + row0 + 8) * T_ + colg] = make_float2(p10, p11);
            }
        }
        __syncthreads();

        // Y += P V
#pragma unroll
        for (int ks2 = 0; ks2 < 8; ks2++) {
            const int kc0 = ks2 * 8;
            uint32_t a0 = __float_as_uint(Ps[(row0    ) * PAD + kc0 + tig]);
            uint32_t a1 = __float_as_uint(Ps[(row0 + 8) * PAD + kc0 + tig]);
            uint32_t a2 = __float_as_uint(Ps[(row0    ) * PAD + kc0 + tig + 4]);
            uint32_t a3 = __float_as_uint(Ps[(row0 + 8) * PAD + kc0 + tig + 4]);
#pragma unroll
            for (int nt = 0; nt < 4; nt++) {
                const int dc = nbase + nt * 8 + gid;
                uint32_t b0 = __float_as_uint(Vs[(kc0 + tig    ) * PAD + dc]);
                uint32_t b1 = __float_as_uint(Vs[(kc0 + tig + 4) * PAD + dc]);
                mma_tf32(yc[nt], a0, a1, a2, a3, b0, b1);
            }
        }
        __syncthreads();
    }

#pragma unroll
    for (int nt = 0; nt < 4; nt++) {
        const int col = nbase + nt * 8 + 2 * tig;
        *(float2*)&g_Y[(size_t)(b * T_ + q0 + row0    ) * C_ + hq * D_ + col] =
            make_float2(yc[nt][0], yc[nt][1]);
        *(float2*)&g_Y[(size_t)(b * T_ + q0 + row0 + 8) * C_ + hq * D_ + col] =
            make_float2(yc[nt][2], yc[nt][3]);
    }
}

// ---------------- launch ----------------
#define FIN_SMEM (4 * 64 * PAD * (int)sizeof(float))   // 69,632 B

extern "C" void kernel_launch(void* const* d_in, const int* in_sizes, int n_in,
                              void* d_out, int out_size)
{
    const float* x  = (const float*)d_in[0];
    const float* Wq = (const float*)d_in[1];
    const float* bq = (const float*)d_in[2];
    const float* Wk = (const float*)d_in[3];
    const float* bk = (const float*)d_in[4];
    const float* Wv = (const float*)d_in[5];
    const float* bv = (const float*)d_in[6];
    const float* Wo = (const float*)d_in[7];
    const float* bo = (const float*)d_in[8];

    // One-time init on the (uncaptured) correctness call.
    static float *qp = nullptr, *kp = nullptr, *vp = nullptr, *yp = nullptr;
    if (!qp) {
        cudaGetSymbolAddress((void**)&qp, g_Q);
        cudaGetSymbolAddress((void**)&kp, g_K);
        cudaGetSymbolAddress((void**)&vp, g_V);
        cudaGetSymbolAddress((void**)&yp, g_Y);
        cudaFuncSetAttribute(attn_finalize_mma,
                             cudaFuncAttributeMaxDynamicSharedMemorySize, FIN_SMEM);
    }

    const size_t yElems   = (size_t)N_ * C_;                       // 8,388,608
    const size_t attElems = (size_t)B_ * G_ * HKV_ * T_ * T_;      // 268,435,456
    float* out = (float*)d_out;
    float* yOut;
    float* attOut;
    int    writeAtt;
    size_t osz = (size_t)out_size;
    if (osz >= yElems + attElems)      { yOut = out; attOut = out + yElems; writeAtt = 1; }
    else if (osz == attElems)          { yOut = qp;  attOut = out;          writeAtt = 1; }
    else                               { yOut = out; attOut = qp;           writeAtt = 0; }

    dim3 blk(256);
    gemm_bias_kernel<<<dim3(C_   / 128, N_ / 128), blk>>>(x, Wq, bq, qp, N_, C_,   C_);
    gemm_bias_kernel<<<dim3(KVC_ / 128, N_ / 128), blk>>>(x, Wk, bk, kp, N_, KVC_, C_);
    gemm_bias_kernel<<<dim3(KVC_ / 128, N_ / 128), blk>>>(x, Wv, bv, vp, N_, KVC_, C_);
    attn_stats_mma   <<<dim3(T_ / 64, B_ * HQ_), blk>>>();
    attn_finalize_mma<<<dim3(T_ / 64, B_ * HQ_), blk, FIN_SMEM>>>(attOut, writeAtt);
    gemm_bias_kernel<<<dim3(C_ / 128, N_ / 128), blk>>>(yp, Wo, bo, yOut, N_, C_, C_);
}

// round 5
// speedup vs baseline: 2.4953x; 1.3395x over previous
#include <cuda_runtime.h>
#include <math.h>
#include <stdint.h>

#define B_   4
#define T_   2048
#define C_   1024
#define HQ_  16
#define HKV_ 4
#define D_   64
#define G_   4
#define N_   (B_*T_)        // 8192 rows
#define KVC_ (HKV_*D_)      // 256
#define PAD  68             // attention smem row stride
#define GP   36             // gemm smem row stride (36 ≡ 4 mod 32 -> conflict-free frags)

// ---------------- scratch (no allocations allowed) ----------------
__device__ float g_Q[(size_t)N_*C_];
__device__ float g_K[(size_t)N_*KVC_];
__device__ float g_V[(size_t)N_*KVC_];
__device__ float g_Y[(size_t)N_*C_];
__device__ float g_M[B_*HQ_*T_];
__device__ float g_L[B_*HQ_*T_];
// pre-transposed + tf32-split weights: [N][K] layout
__device__ float g_Wqh[(size_t)C_*C_],   g_Wql[(size_t)C_*C_];
__device__ float g_Wkh[(size_t)KVC_*C_], g_Wkl[(size_t)KVC_*C_];
__device__ float g_Wvh[(size_t)KVC_*C_], g_Wvl[(size_t)KVC_*C_];
__device__ float g_Woh[(size_t)C_*C_],   g_Wol[(size_t)C_*C_];

// ---------------- tf32 mma helpers ----------------
__device__ __forceinline__ void mma_tf32(float c[4],
    uint32_t a0, uint32_t a1, uint32_t a2, uint32_t a3,
    uint32_t b0, uint32_t b1)
{
    asm volatile(
        "mma.sync.aligned.m16n8k8.row.col.f32.tf32.tf32.f32 "
        "{%0,%1,%2,%3}, {%4,%5,%6,%7}, {%8,%9}, {%0,%1,%2,%3};\n"
        : "+f"(c[0]), "+f"(c[1]), "+f"(c[2]), "+f"(c[3])
        : "r"(a0), "r"(a1), "r"(a2), "r"(a3), "r"(b0), "r"(b1));
}
__device__ __forceinline__ float tf32rn(float x)
{
    uint32_t u;
    asm("cvt.rna.tf32.f32 %0, %1;" : "=r"(u) : "f"(x));
    return __uint_as_float(u);
}

// ---------------- weight prep: transpose + split hi/lo ----------------
// W[K][N] -> Th/Tl[N][K]; 32x32 tiles, block (32,8)
__global__ void transpose_split(const float* __restrict__ W,
                                float* __restrict__ Th, float* __restrict__ Tl,
                                int K, int N)
{
    __shared__ float s[32][33];
    const int n0 = blockIdx.x * 32, k0 = blockIdx.y * 32;
    const int tx = threadIdx.x, ty = threadIdx.y;
#pragma unroll
    for (int i = 0; i < 32; i += 8)
        s[ty + i][tx] = W[(size_t)(k0 + ty + i) * N + n0 + tx];
    __syncthreads();
#pragma unroll
    for (int i = 0; i < 32; i += 8) {
        float v = s[tx][ty + i];
        float h = tf32rn(v);
        float l = tf32rn(v - h);
        Th[(size_t)(n0 + ty + i) * K + k0 + tx] = h;
        Tl[(size_t)(n0 + ty + i) * K + k0 + tx] = l;
    }
}

// ---------------- split-tf32 GEMM: C = A[M,K] @ Bt^T + bias ----------------
// Bt = pre-transposed hi/lo weights [N][K]. A split on the fly.
// 128x128x32 tile, 256 thr = 8 warps: warp = (mw=w&3: 32 rows) x (nw=w>>2: 64 cols).
__global__ __launch_bounds__(256) void gemm_mma3(
    const float* __restrict__ A,
    const float* __restrict__ Bth, const float* __restrict__ Btl,
    const float* __restrict__ bias, float* __restrict__ Cm,
    int M, int N, int K)
{
    extern __shared__ float sm[];
    float* Ah = sm;
    float* Al = sm + 128 * GP;
    float* Bh = sm + 2 * 128 * GP;
    float* Bl = sm + 3 * 128 * GP;

    const int tid  = threadIdx.x;
    const int w    = tid >> 5;
    const int lane = tid & 31;
    const int gid  = lane >> 2;
    const int tig  = lane & 3;
    const int mw   = w & 3;
    const int nw   = w >> 2;
    const int row0 = blockIdx.y * 128, col0 = blockIdx.x * 128;
    const int rA0  = mw * 32 + gid;
    const int cB0  = nw * 64;

    float acc[2][8][4];
#pragma unroll
    for (int m = 0; m < 2; m++)
#pragma unroll
        for (int n = 0; n < 8; n++)
#pragma unroll
            for (int e = 0; e < 4; e++) acc[m][n][e] = 0.f;

    for (int k0 = 0; k0 < K; k0 += 32) {
#pragma unroll
        for (int i = 0; i < 4; i++) {
            int idx4 = tid + i * 256;             // 0..1023
            int r = idx4 >> 3, k4 = (idx4 & 7) << 2;
            float4 v = *(const float4*)&A[(size_t)(row0 + r) * K + k0 + k4];
            float4 h, l;
            h.x = tf32rn(v.x); l.x = tf32rn(v.x - h.x);
            h.y = tf32rn(v.y); l.y = tf32rn(v.y - h.y);
            h.z = tf32rn(v.z); l.z = tf32rn(v.z - h.z);
            h.w = tf32rn(v.w); l.w = tf32rn(v.w - h.w);
            *(float4*)&Ah[r * GP + k4] = h;
            *(float4*)&Al[r * GP + k4] = l;
            *(float4*)&Bh[r * GP + k4] =
                *(const float4*)&Bth[(size_t)(col0 + r) * K + k0 + k4];
            *(float4*)&Bl[r * GP + k4] =
                *(const float4*)&Btl[(size_t)(col0 + r) * K + k0 + k4];
        }
        __syncthreads();

#pragma unroll
        for (int kk = 0; kk < 32; kk += 8) {
            uint32_t ah[2][4], al[2][4];
#pragma unroll
            for (int m = 0; m < 2; m++) {
                const int base = (rA0 + m * 16) * GP + kk;
                ah[m][0] = __float_as_uint(Ah[base + tig]);
                ah[m][1] = __float_as_uint(Ah[base + 8 * GP + tig]);
                ah[m][2] = __float_as_uint(Ah[base + tig + 4]);
                ah[m][3] = __float_as_uint(Ah[base + 8 * GP + tig + 4]);
                al[m][0] = __float_as_uint(Al[base + tig]);
                al[m][1] = __float_as_uint(Al[base + 8 * GP + tig]);
                al[m][2] = __float_as_uint(Al[base + tig + 4]);
                al[m][3] = __float_as_uint(Al[base + 8 * GP + tig + 4]);
            }
#pragma unroll
            for (int n = 0; n < 8; n++) {
                const int cb = (cB0 + n * 8 + gid) * GP + kk;
                uint32_t bh0 = __float_as_uint(Bh[cb + tig]);
                uint32_t bh1 = __float_as_uint(Bh[cb + tig + 4]);
                uint32_t bl0 = __float_as_uint(Bl[cb + tig]);
                uint32_t bl1 = __float_as_uint(Bl[cb + tig + 4]);
                mma_tf32(acc[0][n], ah[0][0], ah[0][1], ah[0][2], ah[0][3], bh0, bh1);
                mma_tf32(acc[1][n], ah[1][0], ah[1][1], ah[1][2], ah[1][3], bh0, bh1);
                mma_tf32(acc[0][n], ah[0][0], ah[0][1], ah[0][2], ah[0][3], bl0, bl1);
                mma_tf32(acc[1][n], ah[1][0], ah[1][1], ah[1][2], ah[1][3], bl0, bl1);
                mma_tf32(acc[0][n], al[0][0], al[0][1], al[0][2], al[0][3], bh0, bh1);
                mma_tf32(acc[1][n], al[1][0], al[1][1], al[1][2], al[1][3], bh0, bh1);
            }
        }
        __syncthreads();
    }

#pragma unroll
    for (int m = 0; m < 2; m++) {
        const int row = row0 + mw * 32 + m * 16 + gid;
#pragma unroll
        for (int n = 0; n < 8; n++) {
            const int col = col0 + cB0 + n * 8 + 2 * tig;
            const float b0 = bias[col], b1 = bias[col + 1];
            *(float2*)&Cm[(size_t)row * N + col] =
                make_float2(acc[m][n][0] + b0, acc[m][n][1] + b1);
            *(float2*)&Cm[(size_t)(row + 8) * N + col] =
                make_float2(acc[m][n][2] + b0, acc[m][n][3] + b1);
        }
    }
}

// ---------------- attention pass 1 (mma): row max + sumexp ----------------
__global__ __launch_bounds__(256) void attn_stats_mma()
{
    __shared__ float Qs[64 * PAD];
    __shared__ float Ks[64 * PAD];
    __shared__ float redM[2][64];
    __shared__ float redL[2][64];

    const int tid  = threadIdx.x;
    const int w    = tid >> 5;
    const int lane = tid & 31;
    const int gid  = lane >> 2;
    const int tig  = lane & 3;
    const int mstrip = w & 3;
    const int nhalf  = w >> 2;
    const int row0  = mstrip * 16 + gid;
    const int nbase = nhalf * 32;

    const int bh = blockIdx.y;
    const int b  = bh >> 4, hq = bh & 15, h = hq >> 2;
    const int q0 = blockIdx.x * 64;

    {
        const float* src = &g_Q[(size_t)(b * T_ + q0) * C_ + hq * D_];
        for (int idx = tid; idx < 1024; idx += 256) {
            int r = idx >> 4, d = (idx & 15) << 2;
            float4 v = *(const float4*)&src[(size_t)r * C_ + d];
            v.x = tf32rn(v.x); v.y = tf32rn(v.y); v.z = tf32rn(v.z); v.w = tf32rn(v.w);
            *(float4*)&Qs[r * PAD + d] = v;
        }
    }

    float runm0 = -1e30f, runs0 = 0.f, runm1 = -1e30f, runs1 = 0.f;
    const int diag = q0 >> 6;

    for (int kt = 0; kt <= diag; kt++) {
        const int k0 = kt * 64;
        const float* ksrc = &g_K[(size_t)(b * T_ + k0) * KVC_ + h * D_];
        for (int idx = tid; idx < 1024; idx += 256) {
            int r = idx >> 4, d = (idx & 15) << 2;
            float4 v = *(const float4*)&ksrc[(size_t)r * KVC_ + d];
            v.x = tf32rn(v.x); v.y = tf32rn(v.y); v.z = tf32rn(v.z); v.w = tf32rn(v.w);
            *(float4*)&Ks[r * PAD + d] = v;
        }
        __syncthreads();

        float c[4][4];
#pragma unroll
        for (int nt = 0; nt < 4; nt++)
#pragma unroll
            for (int e = 0; e < 4; e++) c[nt][e] = 0.f;

#pragma unroll
        for (int ks2 = 0; ks2 < 8; ks2++) {
            const int d0 = ks2 * 8;
            uint32_t a0 = __float_as_uint(Qs[(row0    ) * PAD + d0 + tig]);
            uint32_t a1 = __float_as_uint(Qs[(row0 + 8) * PAD + d0 + tig]);
            uint32_t a2 = __float_as_uint(Qs[(row0    ) * PAD + d0 + tig + 4]);
            uint32_t a3 = __float_as_uint(Qs[(row0 + 8) * PAD + d0 + tig + 4]);
#pragma unroll
            for (int nt = 0; nt < 4; nt++) {
                const int nc = nbase + nt * 8 + gid;
                uint32_t b0 = __float_as_uint(Ks[nc * PAD + d0 + tig]);
                uint32_t b1 = __float_as_uint(Ks[nc * PAD + d0 + tig + 4]);
                mma_tf32(c[nt], a0, a1, a2, a3, b0, b1);
            }
        }

        const bool dm = (kt == diag);
#pragma unroll
        for (int nt = 0; nt < 4; nt++) {
            const int colb = k0 + nbase + nt * 8 + 2 * tig;
#pragma unroll
            for (int e = 0; e < 2; e++) {
                float v0 = c[nt][e]     * 0.125f;
                float v1 = c[nt][2 + e] * 0.125f;
                if (dm && colb + e > q0 + row0    ) v0 = -1e30f;
                if (dm && colb + e > q0 + row0 + 8) v1 = -1e30f;
                c[nt][e] = v0; c[nt][2 + e] = v1;
            }
        }

        float m0 = c[0][0], m1 = c[0][2];
#pragma unroll
        for (int nt = 0; nt < 4; nt++) {
            m0 = fmaxf(m0, fmaxf(c[nt][0], c[nt][1]));
            m1 = fmaxf(m1, fmaxf(c[nt][2], c[nt][3]));
        }
        m0 = fmaxf(m0, __shfl_xor_sync(0xffffffffu, m0, 1));
        m0 = fmaxf(m0, __shfl_xor_sync(0xffffffffu, m0, 2));
        m1 = fmaxf(m1, __shfl_xor_sync(0xffffffffu, m1, 1));
        m1 = fmaxf(m1, __shfl_xor_sync(0xffffffffu, m1, 2));

        const float nm0 = fmaxf(runm0, m0);
        const float nm1 = fmaxf(runm1, m1);
        float s0 = 0.f, s1 = 0.f;
#pragma unroll
        for (int nt = 0; nt < 4; nt++) {
            s0 += __expf(c[nt][0] - nm0) + __expf(c[nt][1] - nm0);
            s1 += __expf(c[nt][2] - nm1) + __expf(c[nt][3] - nm1);
        }
        s0 += __shfl_xor_sync(0xffffffffu, s0, 1);
        s0 += __shfl_xor_sync(0xffffffffu, s0, 2);
        s1 += __shfl_xor_sync(0xffffffffu, s1, 1);
        s1 += __shfl_xor_sync(0xffffffffu, s1, 2);

        runs0 = runs0 * __expf(runm0 - nm0) + s0;  runm0 = nm0;
        runs1 = runs1 * __expf(runm1 - nm1) + s1;  runm1 = nm1;
        __syncthreads();
    }

    if (tig == 0) {
        redM[nhalf][row0]     = runm0;  redL[nhalf][row0]     = runs0;
        redM[nhalf][row0 + 8] = runm1;  redL[nhalf][row0 + 8] = runs1;
    }
    __syncthreads();
    if (nhalf == 0 && tig == 0) {
#pragma unroll
        for (int rr = 0; rr < 2; rr++) {
            const int r = row0 + rr * 8;
            const float ma = redM[0][r], mb = redM[1][r];
            const float m  = fmaxf(ma, mb);
            const float l  = redL[0][r] * __expf(ma - m) + redL[1][r] * __expf(mb - m);
            g_M[bh * T_ + q0 + r] = m;
            g_L[bh * T_ + q0 + r] = l;
        }
    }
}

// ---------------- attention pass 2 (mma): P write + Y accumulate ----------------
__global__ __launch_bounds__(256) void attn_finalize_mma(float* __restrict__ att,
                                                         int write_att)
{
    extern __shared__ float smdyn[];
    float* Qs = smdyn;
    float* Ks = smdyn + 64 * PAD;
    float* Vs = smdyn + 2 * 64 * PAD;
    float* Ps = smdyn + 3 * 64 * PAD;

    const int tid  = threadIdx.x;
    const int w    = tid >> 5;
    const int lane = tid & 31;
    const int gid  = lane >> 2;
    const int tig  = lane & 3;
    const int mstrip = w & 3;
    const int nhalf  = w >> 2;
    const int row0  = mstrip * 16 + gid;
    const int nbase = nhalf * 32;

    const int bh = blockIdx.y;
    const int b  = bh >> 4, hq = bh & 15, h = hq >> 2, g = hq & 3;
    const int q0 = blockIdx.x * 64;
    const size_t attbase = (size_t)((b * G_ + g) * HKV_ + h) * T_ * T_;

    {
        const float* src = &g_Q[(size_t)(b * T_ + q0) * C_ + hq * D_];
        for (int idx = tid; idx < 1024; idx += 256) {
            int r = idx >> 4, d = (idx & 15) << 2;
            float4 v = *(const float4*)&src[(size_t)r * C_ + d];
            v.x = tf32rn(v.x); v.y = tf32rn(v.y); v.z = tf32rn(v.z); v.w = tf32rn(v.w);
            *(float4*)&Qs[r * PAD + d] = v;
        }
    }

    const float mr0 = g_M[bh * T_ + q0 + row0];
    const float li0 = 1.f / g_L[bh * T_ + q0 + row0];
    const float mr1 = g_M[bh * T_ + q0 + row0 + 8];
    const float li1 = 1.f / g_L[bh * T_ + q0 + row0 + 8];

    float yc[4][4];
#pragma unroll
    for (int nt = 0; nt < 4; nt++)
#pragma unroll
        for (int e = 0; e < 4; e++) yc[nt][e] = 0.f;

    const int diag = q0 >> 6;
    for (int kt = 0; kt < T_ / 64; kt++) {
        const int k0 = kt * 64;
        if (kt > diag) {
            if (write_att) {
                const float4 z = make_float4(0.f, 0.f, 0.f, 0.f);
                for (int idx = tid; idx < 1024; idx += 256) {
                    int r = idx >> 4, cc = (idx & 15) << 2;
                    *(float4*)&att[attbase + (size_t)(q0 + r) * T_ + k0 + cc] = z;
                }
            }
            continue;
        }

        {
            const float* ksrc = &g_K[(size_t)(b * T_ + k0) * KVC_ + h * D_];
            const float* vsrc = &g_V[(size_t)(b * T_ + k0) * KVC_ + h * D_];
            for (int idx = tid; idx < 1024; idx += 256) {
                int r = idx >> 4, d = (idx & 15) << 2;
                float4 kv = *(const float4*)&ksrc[(size_t)r * KVC_ + d];
                float4 vv = *(const float4*)&vsrc[(size_t)r * KVC_ + d];
                kv.x = tf32rn(kv.x); kv.y = tf32rn(kv.y); kv.z = tf32rn(kv.z); kv.w = tf32rn(kv.w);
                vv.x = tf32rn(vv.x); vv.y = tf32rn(vv.y); vv.z = tf32rn(vv.z); vv.w = tf32rn(vv.w);
                *(float4*)&Ks[r * PAD + d] = kv;
                *(float4*)&Vs[r * PAD + d] = vv;
            }
        }
        __syncthreads();

        float c[4][4];
#pragma unroll
        for (int nt = 0; nt < 4; nt++)
#pragma unroll
            for (int e = 0; e < 4; e++) c[nt][e] = 0.f;
#pragma unroll
        for (int ks2 = 0; ks2 < 8; ks2++) {
            const int d0 = ks2 * 8;
            uint32_t a0 = __float_as_uint(Qs[(row0    ) * PAD + d0 + tig]);
            uint32_t a1 = __float_as_uint(Qs[(row0 + 8) * PAD + d0 + tig]);
            uint32_t a2 = __float_as_uint(Qs[(row0    ) * PAD + d0 + tig + 4]);
            uint32_t a3 = __float_as_uint(Qs[(row0 + 8) * PAD + d0 + tig + 4]);
#pragma unroll
            for (int nt = 0; nt < 4; nt++) {
                const int nc = nbase + nt * 8 + gid;
                uint32_t b0 = __float_as_uint(Ks[nc * PAD + d0 + tig]);
                uint32_t b1 = __float_as_uint(Ks[nc * PAD + d0 + tig + 4]);
                mma_tf32(c[nt], a0, a1, a2, a3, b0, b1);
            }
        }

        const bool dm = (kt == diag);
#pragma unroll
        for (int nt = 0; nt < 4; nt++) {
            const int col  = nbase + nt * 8 + 2 * tig;
            const int colg = k0 + col;
            float v00 = c[nt][0] * 0.125f, v01 = c[nt][1] * 0.125f;
            float v10 = c[nt][2] * 0.125f, v11 = c[nt][3] * 0.125f;
            if (dm) {
                if (colg     > q0 + row0    ) v00 = -1e30f;
                if (colg + 1 > q0 + row0    ) v01 = -1e30f;
                if (colg     > q0 + row0 + 8) v10 = -1e30f;
                if (colg + 1 > q0 + row0 + 8) v11 = -1e30f;
            }
            const float p00 = __expf(v00 - mr0) * li0;
            const float p01 = __expf(v01 - mr0) * li0;
            const float p10 = __expf(v10 - mr1) * li1;
            const float p11 = __expf(v11 - mr1) * li1;
            *(float2*)&Ps[(row0    ) * PAD + col] = make_float2(tf32rn(p00), tf32rn(p01));
            *(float2*)&Ps[(row0 + 8) * PAD + col] = make_float2(tf32rn(p10), tf32rn(p11));
            if (write_att) {
                *(float2*)&att[attbase + (size_t)(q0 + row0    ) * T_ + colg] = make_float2(p00, p01);
                *(float2*)&att[attbase + (size_t)(q0 + row0 + 8) * T_ + colg] = make_float2(p10, p11);
            }
        }
        __syncthreads();

#pragma unroll
        for (int ks2 = 0; ks2 < 8; ks2++) {
            const int kc0 = ks2 * 8;
            uint32_t a0 = __float_as_uint(Ps[(row0    ) * PAD + kc0 + tig]);
            uint32_t a1 = __float_as_uint(Ps[(row0 + 8) * PAD + kc0 + tig]);
            uint32_t a2 = __float_as_uint(Ps[(row0    ) * PAD + kc0 + tig + 4]);
            uint32_t a3 = __float_as_uint(Ps[(row0 + 8) * PAD + kc0 + tig + 4]);
#pragma unroll
            for (int nt = 0; nt < 4; nt++) {
                const int dc = nbase + nt * 8 + gid;
                uint32_t b0 = __float_as_uint(Vs[(kc0 + tig    ) * PAD + dc]);
                uint32_t b1 = __float_as_uint(Vs[(kc0 + tig + 4) * PAD + dc]);
                mma_tf32(yc[nt], a0, a1, a2, a3, b0, b1);
            }
        }
        __syncthreads();
    }

#pragma unroll
    for (int nt = 0; nt < 4; nt++) {
        const int col = nbase + nt * 8 + 2 * tig;
        *(float2*)&g_Y[(size_t)(b * T_ + q0 + row0    ) * C_ + hq * D_ + col] =
            make_float2(yc[nt][0], yc[nt][1]);
        *(float2*)&g_Y[(size_t)(b * T_ + q0 + row0 + 8) * C_ + hq * D_ + col] =
            make_float2(yc[nt][2], yc[nt][3]);
    }
}

// ---------------- launch ----------------
#define FIN_SMEM  (4 * 64 * PAD * (int)sizeof(float))   // 69,632 B
#define GEMM_SMEM (4 * 128 * GP * (int)sizeof(float))   // 73,728 B

extern "C" void kernel_launch(void* const* d_in, const int* in_sizes, int n_in,
                              void* d_out, int out_size)
{
    const float* x  = (const float*)d_in[0];
    const float* Wq = (const float*)d_in[1];
    const float* bq = (const float*)d_in[2];
    const float* Wk = (const float*)d_in[3];
    const float* bk = (const float*)d_in[4];
    const float* Wv = (const float*)d_in[5];
    const float* bv = (const float*)d_in[6];
    const float* Wo = (const float*)d_in[7];
    const float* bo = (const float*)d_in[8];

    static float *qp = nullptr, *kp = nullptr, *vp = nullptr, *yp = nullptr;
    static float *wqh, *wql, *wkh, *wkl, *wvh, *wvl, *woh, *wol;
    if (!qp) {
        cudaGetSymbolAddress((void**)&qp,  g_Q);
        cudaGetSymbolAddress((void**)&kp,  g_K);
        cudaGetSymbolAddress((void**)&vp,  g_V);
        cudaGetSymbolAddress((void**)&yp,  g_Y);
        cudaGetSymbolAddress((void**)&wqh, g_Wqh);
        cudaGetSymbolAddress((void**)&wql, g_Wql);
        cudaGetSymbolAddress((void**)&wkh, g_Wkh);
        cudaGetSymbolAddress((void**)&wkl, g_Wkl);
        cudaGetSymbolAddress((void**)&wvh, g_Wvh);
        cudaGetSymbolAddress((void**)&wvl, g_Wvl);
        cudaGetSymbolAddress((void**)&woh, g_Woh);
        cudaGetSymbolAddress((void**)&wol, g_Wol);
        cudaFuncSetAttribute(attn_finalize_mma,
                             cudaFuncAttributeMaxDynamicSharedMemorySize, FIN_SMEM);
        cudaFuncSetAttribute(gemm_mma3,
                             cudaFuncAttributeMaxDynamicSharedMemorySize, GEMM_SMEM);
    }

    const size_t yElems   = (size_t)N_ * C_;
    const size_t attElems = (size_t)B_ * G_ * HKV_ * T_ * T_;
    float* out = (float*)d_out;
    float* yOut;
    float* attOut;
    int    writeAtt;
    size_t osz = (size_t)out_size;
    if (osz >= yElems + attElems)      { yOut = out; attOut = out + yElems; writeAtt = 1; }
    else if (osz == attElems)          { yOut = qp;  attOut = out;          writeAtt = 1; }
    else                               { yOut = out; attOut = qp;           writeAtt = 0; }

    dim3 blk(256);
    dim3 tb(32, 8);
    transpose_split<<<dim3(C_   / 32, C_ / 32), tb>>>(Wq, wqh, wql, C_, C_);
    transpose_split<<<dim3(KVC_ / 32, C_ / 32), tb>>>(Wk, wkh, wkl, C_, KVC_);
    transpose_split<<<dim3(KVC_ / 32, C_ / 32), tb>>>(Wv, wvh, wvl, C_, KVC_);
    transpose_split<<<dim3(C_   / 32, C_ / 32), tb>>>(Wo, woh, wol, C_, C_);

    gemm_mma3<<<dim3(C_   / 128, N_ / 128), blk, GEMM_SMEM>>>(x, wqh, wql, bq, qp, N_, C_,   C_);
    gemm_mma3<<<dim3(KVC_ / 128, N_ / 128), blk, GEMM_SMEM>>>(x, wkh, wkl, bk, kp, N_, KVC_, C_);
    gemm_mma3<<<dim3(KVC_ / 128, N_ / 128), blk, GEMM_SMEM>>>(x, wvh, wvl, bv, vp, N_, KVC_, C_);

    attn_stats_mma   <<<dim3(T_ / 64, B_ * HQ_), blk>>>();
    attn_finalize_mma<<<dim3(T_ / 64, B_ * HQ_), blk, FIN_SMEM>>>(attOut, writeAtt);

    gemm_mma3<<<dim3(C_ / 128, N_ / 128), blk, GEMM_SMEM>>>(yp, woh, wol, bo, yOut, N_, C_, C_);
}

// round 7
// speedup vs baseline: 3.1235x; 1.2517x over previous
// R7 = R6 resubmitted unchanged: R6 was a GPUAcquisitionTimeout (broker capacity),
// the bf16x3 GEMM change has not yet been measured.
#include <cuda_runtime.h>
#include <cuda_bf16.h>
#include <math.h>
#include <stdint.h>

#define B_   4
#define T_   2048
#define C_   1024
#define HQ_  16
#define HKV_ 4
#define D_   64
#define G_   4
#define N_   (B_*T_)        // 8192 rows
#define KVC_ (HKV_*D_)      // 256
#define PAD  68             // attention smem row stride (floats)
#define GKP  40             // gemm smem row stride in bf16 elems (80B = 20 words)

// ---------------- scratch (no allocations allowed) ----------------
__device__ float g_Q[(size_t)N_*C_];
__device__ float g_K[(size_t)N_*KVC_];
__device__ float g_V[(size_t)N_*KVC_];
__device__ float g_Y[(size_t)N_*C_];
__device__ float g_M[B_*HQ_*T_];
__device__ float g_L[B_*HQ_*T_];
// pre-transposed + bf16-split weights: [N][K]
__device__ __nv_bfloat16 g_Wqh[(size_t)C_*C_],   g_Wql[(size_t)C_*C_];
__device__ __nv_bfloat16 g_Wkh[(size_t)KVC_*C_], g_Wkl[(size_t)KVC_*C_];
__device__ __nv_bfloat16 g_Wvh[(size_t)KVC_*C_], g_Wvl[(size_t)KVC_*C_];
__device__ __nv_bfloat16 g_Woh[(size_t)C_*C_],   g_Wol[(size_t)C_*C_];

// ---------------- mma helpers ----------------
__device__ __forceinline__ void mma_tf32(float c[4],
    uint32_t a0, uint32_t a1, uint32_t a2, uint32_t a3,
    uint32_t b0, uint32_t b1)
{
    asm volatile(
        "mma.sync.aligned.m16n8k8.row.col.f32.tf32.tf32.f32 "
        "{%0,%1,%2,%3}, {%4,%5,%6,%7}, {%8,%9}, {%0,%1,%2,%3};\n"
        : "+f"(c[0]), "+f"(c[1]), "+f"(c[2]), "+f"(c[3])
        : "r"(a0), "r"(a1), "r"(a2), "r"(a3), "r"(b0), "r"(b1));
}
__device__ __forceinline__ void mma_bf16(float c[4],
    uint32_t a0, uint32_t a1, uint32_t a2, uint32_t a3,
    uint32_t b0, uint32_t b1)
{
    asm volatile(
        "mma.sync.aligned.m16n8k16.row.col.f32.bf16.bf16.f32 "
        "{%0,%1,%2,%3}, {%4,%5,%6,%7}, {%8,%9}, {%0,%1,%2,%3};\n"
        : "+f"(c[0]), "+f"(c[1]), "+f"(c[2]), "+f"(c[3])
        : "r"(a0), "r"(a1), "r"(a2), "r"(a3), "r"(b0), "r"(b1));
}
__device__ __forceinline__ float tf32rn(float x)
{
    uint32_t u;
    asm("cvt.rna.tf32.f32 %0, %1;" : "=r"(u) : "f"(x));
    return __uint_as_float(u);
}
__device__ __forceinline__ uint32_t pack_bf2(float x, float y)
{
    __nv_bfloat162 t = __floats2bfloat162_rn(x, y);   // .x = x (low half)
    return *(uint32_t*)&t;
}

// ---------------- weight prep: transpose + bf16 hi/lo split ----------------
// W[K][N] fp32 -> Th/Tl[N][K] bf16; 32x32 tiles, block (32,8)
__global__ void transpose_split(const float* __restrict__ W,
                                __nv_bfloat16* __restrict__ Th,
                                __nv_bfloat16* __restrict__ Tl,
                                int K, int N)
{
    __shared__ float s[32][33];
    const int n0 = blockIdx.x * 32, k0 = blockIdx.y * 32;
    const int tx = threadIdx.x, ty = threadIdx.y;
#pragma unroll
    for (int i = 0; i < 32; i += 8)
        s[ty + i][tx] = W[(size_t)(k0 + ty + i) * N + n0 + tx];
    __syncthreads();
#pragma unroll
    for (int i = 0; i < 32; i += 8) {
        float v = s[tx][ty + i];
        __nv_bfloat16 h = __float2bfloat16_rn(v);
        __nv_bfloat16 l = __float2bfloat16_rn(v - __bfloat162float(h));
        Th[(size_t)(n0 + ty + i) * K + k0 + tx] = h;
        Tl[(size_t)(n0 + ty + i) * K + k0 + tx] = l;
    }
}

// ---------------- bf16x3 GEMM: C = A[M,K] @ Bt^T + bias ----------------
// Bt = pre-split bf16 weights [N][K]. A split on the fly to bf16 hi/lo.
// 128x128x32 tile, 256 thr = 8 warps: warp = (mw=w&3: 32 rows) x (nw=w>>2: 64 cols).
__global__ __launch_bounds__(256) void gemm_bf16x3(
    const float* __restrict__ A,
    const __nv_bfloat16* __restrict__ Bth, const __nv_bfloat16* __restrict__ Btl,
    const float* __restrict__ bias, float* __restrict__ Cm,
    int M, int N, int K)
{
    __shared__ __nv_bfloat16 Ah[128 * GKP], Al[128 * GKP];
    __shared__ __nv_bfloat16 Bh[128 * GKP], Bl[128 * GKP];
    uint32_t* Ahu = (uint32_t*)Ah;  uint32_t* Alu = (uint32_t*)Al;
    uint32_t* Bhu = (uint32_t*)Bh;  uint32_t* Blu = (uint32_t*)Bl;

    const int tid  = threadIdx.x;
    const int w    = tid >> 5;
    const int lane = tid & 31;
    const int gid  = lane >> 2;
    const int tig  = lane & 3;
    const int mw   = w & 3;
    const int nw   = w >> 2;
    const int row0 = blockIdx.y * 128, col0 = blockIdx.x * 128;
    const int cB0  = nw * 64;

    float acc[2][8][4];
#pragma unroll
    for (int m = 0; m < 2; m++)
#pragma unroll
        for (int n = 0; n < 8; n++)
#pragma unroll
            for (int e = 0; e < 4; e++) acc[m][n][e] = 0.f;

    for (int k0 = 0; k0 < K; k0 += 32) {
        // A: 128x32 fp32 -> split bf16 hi/lo
#pragma unroll
        for (int i = 0; i < 4; i++) {
            int idx4 = tid + i * 256;              // 0..1023
            int r = idx4 >> 3, k4 = (idx4 & 7) << 2;
            float4 v = *(const float4*)&A[(size_t)(row0 + r) * K + k0 + k4];
            float hx = __bfloat162float(__float2bfloat16_rn(v.x));
            float hy = __bfloat162float(__float2bfloat16_rn(v.y));
            float hz = __bfloat162float(__float2bfloat16_rn(v.z));
            float hw = __bfloat162float(__float2bfloat16_rn(v.w));
            int ui = r * (GKP / 2) + (k4 >> 1);
            Ahu[ui]     = pack_bf2(hx, hy);
            Ahu[ui + 1] = pack_bf2(hz, hw);
            Alu[ui]     = pack_bf2(v.x - hx, v.y - hy);
            Alu[ui + 1] = pack_bf2(v.z - hz, v.w - hw);
        }
        // B: 128x32 bf16 hi/lo direct copy (16B chunks)
#pragma unroll
        for (int i = 0; i < 2; i++) {
            int idx8 = tid + i * 256;              // 0..511
            int r = idx8 >> 2, k8 = (idx8 & 3) << 3;
            const uint4 bh = *(const uint4*)&Bth[(size_t)(col0 + r) * K + k0 + k8];
            const uint4 bl = *(const uint4*)&Btl[(size_t)(col0 + r) * K + k0 + k8];
            *(uint4*)&Bhu[r * (GKP / 2) + (k8 >> 1)] = bh;
            *(uint4*)&Blu[r * (GKP / 2) + (k8 >> 1)] = bl;
        }
        __syncthreads();

#pragma unroll
        for (int kk = 0; kk < 32; kk += 16) {
            const int kw = (kk >> 1) + tig;        // uint offset within row
            uint32_t ah[2][4], al[2][4];
#pragma unroll
            for (int m = 0; m < 2; m++) {
                const int rm = mw * 32 + m * 16 + gid;
                ah[m][0] = Ahu[ rm      * (GKP / 2) + kw];
                ah[m][1] = Ahu[(rm + 8) * (GKP / 2) + kw];
                ah[m][2] = Ahu[ rm      * (GKP / 2) + kw + 4];
                ah[m][3] = Ahu[(rm + 8) * (GKP / 2) + kw + 4];
                al[m][0] = Alu[ rm      * (GKP / 2) + kw];
                al[m][1] = Alu[(rm + 8) * (GKP / 2) + kw];
                al[m][2] = Alu[ rm      * (GKP / 2) + kw + 4];
                al[m][3] = Alu[(rm + 8) * (GKP / 2) + kw + 4];
            }
#pragma unroll
            for (int n = 0; n < 8; n++) {
                const int cn = (cB0 + n * 8 + gid) * (GKP / 2) + kw;
                uint32_t bh0 = Bhu[cn], bh1 = Bhu[cn + 4];
                uint32_t bl0 = Blu[cn], bl1 = Blu[cn + 4];
                mma_bf16(acc[0][n], ah[0][0], ah[0][1], ah[0][2], ah[0][3], bh0, bh1);
                mma_bf16(acc[1][n], ah[1][0], ah[1][1], ah[1][2], ah[1][3], bh0, bh1);
                mma_bf16(acc[0][n], ah[0][0], ah[0][1], ah[0][2], ah[0][3], bl0, bl1);
                mma_bf16(acc[1][n], ah[1][0], ah[1][1], ah[1][2], ah[1][3], bl0, bl1);
                mma_bf16(acc[0][n], al[0][0], al[0][1], al[0][2], al[0][3], bh0, bh1);
                mma_bf16(acc[1][n], al[1][0], al[1][1], al[1][2], al[1][3], bh0, bh1);
            }
        }
        __syncthreads();
    }

#pragma unroll
    for (int m = 0; m < 2; m++) {
        const int row = row0 + mw * 32 + m * 16 + gid;
#pragma unroll
        for (int n = 0; n < 8; n++) {
            const int col = col0 + cB0 + n * 8 + 2 * tig;
            const float b0 = bias[col], b1 = bias[col + 1];
            *(float2*)&Cm[(size_t)row * N + col] =
                make_float2(acc[m][n][0] + b0, acc[m][n][1] + b1);
            *(float2*)&Cm[(size_t)(row + 8) * N + col] =
                make_float2(acc[m][n][2] + b0, acc[m][n][3] + b1);
        }
    }
}

// ---------------- attention pass 1 (mma): row max + sumexp ----------------
__global__ __launch_bounds__(256) void attn_stats_mma()
{
    __shared__ float Qs[64 * PAD];
    __shared__ float Ks[64 * PAD];
    __shared__ float redM[2][64];
    __shared__ float redL[2][64];

    const int tid  = threadIdx.x;
    const int w    = tid >> 5;
    const int lane = tid & 31;
    const int gid  = lane >> 2;
    const int tig  = lane & 3;
    const int mstrip = w & 3;
    const int nhalf  = w >> 2;
    const int row0  = mstrip * 16 + gid;
    const int nbase = nhalf * 32;

    const int bh = blockIdx.y;
    const int b  = bh >> 4, hq = bh & 15, h = hq >> 2;
    const int q0 = blockIdx.x * 64;

    {
        const float* src = &g_Q[(size_t)(b * T_ + q0) * C_ + hq * D_];
        for (int idx = tid; idx < 1024; idx += 256) {
            int r = idx >> 4, d = (idx & 15) << 2;
            float4 v = *(const float4*)&src[(size_t)r * C_ + d];
            v.x = tf32rn(v.x); v.y = tf32rn(v.y); v.z = tf32rn(v.z); v.w = tf32rn(v.w);
            *(float4*)&Qs[r * PAD + d] = v;
        }
    }

    float runm0 = -1e30f, runs0 = 0.f, runm1 = -1e30f, runs1 = 0.f;
    const int diag = q0 >> 6;

    for (int kt = 0; kt <= diag; kt++) {
        const int k0 = kt * 64;
        const float* ksrc = &g_K[(size_t)(b * T_ + k0) * KVC_ + h * D_];
        for (int idx = tid; idx < 1024; idx += 256) {
            int r = idx >> 4, d = (idx & 15) << 2;
            float4 v = *(const float4*)&ksrc[(size_t)r * KVC_ + d];
            v.x = tf32rn(v.x); v.y = tf32rn(v.y); v.z = tf32rn(v.z); v.w = tf32rn(v.w);
            *(float4*)&Ks[r * PAD + d] = v;
        }
        __syncthreads();

        float c[4][4];
#pragma unroll
        for (int nt = 0; nt < 4; nt++)
#pragma unroll
            for (int e = 0; e < 4; e++) c[nt][e] = 0.f;

#pragma unroll
        for (int ks2 = 0; ks2 < 8; ks2++) {
            const int d0 = ks2 * 8;
            uint32_t a0 = __float_as_uint(Qs[(row0    ) * PAD + d0 + tig]);
            uint32_t a1 = __float_as_uint(Qs[(row0 + 8) * PAD + d0 + tig]);
            uint32_t a2 = __float_as_uint(Qs[(row0    ) * PAD + d0 + tig + 4]);
            uint32_t a3 = __float_as_uint(Qs[(row0 + 8) * PAD + d0 + tig + 4]);
#pragma unroll
            for (int nt = 0; nt < 4; nt++) {
                const int nc = nbase + nt * 8 + gid;
                uint32_t b0 = __float_as_uint(Ks[nc * PAD + d0 + tig]);
                uint32_t b1 = __float_as_uint(Ks[nc * PAD + d0 + tig + 4]);
                mma_tf32(c[nt], a0, a1, a2, a3, b0, b1);
            }
        }

        const bool dm = (kt == diag);
#pragma unroll
        for (int nt = 0; nt < 4; nt++) {
            const int colb = k0 + nbase + nt * 8 + 2 * tig;
#pragma unroll
            for (int e = 0; e < 2; e++) {
                float v0 = c[nt][e]     * 0.125f;
                float v1 = c[nt][2 + e] * 0.125f;
                if (dm && colb + e > q0 + row0    ) v0 = -1e30f;
                if (dm && colb + e > q0 + row0 + 8) v1 = -1e30f;
                c[nt][e] = v0; c[nt][2 + e] = v1;
            }
        }

        float m0 = c[0][0], m1 = c[0][2];
#pragma unroll
        for (int nt = 0; nt < 4; nt++) {
            m0 = fmaxf(m0, fmaxf(c[nt][0], c[nt][1]));
            m1 = fmaxf(m1, fmaxf(c[nt][2], c[nt][3]));
        }
        m0 = fmaxf(m0, __shfl_xor_sync(0xffffffffu, m0, 1));
        m0 = fmaxf(m0, __shfl_xor_sync(0xffffffffu, m0, 2));
        m1 = fmaxf(m1, __shfl_xor_sync(0xffffffffu, m1, 1));
        m1 = fmaxf(m1, __shfl_xor_sync(0xffffffffu, m1, 2));

        const float nm0 = fmaxf(runm0, m0);
        const float nm1 = fmaxf(runm1, m1);
        float s0 = 0.f, s1 = 0.f;
#pragma unroll
        for (int nt = 0; nt < 4; nt++) {
            s0 += __expf(c[nt][0] - nm0) + __expf(c[nt][1] - nm0);
            s1 += __expf(c[nt][2] - nm1) + __expf(c[nt][3] - nm1);
        }
        s0 += __shfl_xor_sync(0xffffffffu, s0, 1);
        s0 += __shfl_xor_sync(0xffffffffu, s0, 2);
        s1 += __shfl_xor_sync(0xffffffffu, s1, 1);
        s1 += __shfl_xor_sync(0xffffffffu, s1, 2);

        runs0 = runs0 * __expf(runm0 - nm0) + s0;  runm0 = nm0;
        runs1 = runs1 * __expf(runm1 - nm1) + s1;  runm1 = nm1;
        __syncthreads();
    }

    if (tig == 0) {
        redM[nhalf][row0]     = runm0;  redL[nhalf][row0]     = runs0;
        redM[nhalf][row0 + 8] = runm1;  redL[nhalf][row0 + 8] = runs1;
    }
    __syncthreads();
    if (nhalf == 0 && tig == 0) {
#pragma unroll
        for (int rr = 0; rr < 2; rr++) {
            const int r = row0 + rr * 8;
            const float ma = redM[0][r], mb = redM[1][r];
            const float m  = fmaxf(ma, mb);
            const float l  = redL[0][r] * __expf(ma - m) + redL[1][r] * __expf(mb - m);
            g_M[bh * T_ + q0 + r] = m;
            g_L[bh * T_ + q0 + r] = l;
        }
    }
}

// ---------------- attention pass 2 (mma): P write + Y accumulate ----------------
__global__ __launch_bounds__(256) void attn_finalize_mma(float* __restrict__ att,
                                                         int write_att)
{
    extern __shared__ float smdyn[];
    float* Qs = smdyn;
    float* Ks = smdyn + 64 * PAD;
    float* Vs = smdyn + 2 * 64 * PAD;
    float* Ps = smdyn + 3 * 64 * PAD;

    const int tid  = threadIdx.x;
    const int w    = tid >> 5;
    const int lane = tid & 31;
    const int gid  = lane >> 2;
    const int tig  = lane & 3;
    const int mstrip = w & 3;
    const int nhalf  = w >> 2;
    const int row0  = mstrip * 16 + gid;
    const int nbase = nhalf * 32;

    const int bh = blockIdx.y;
    const int b  = bh >> 4, hq = bh & 15, h = hq >> 2, g = hq & 3;
    const int q0 = blockIdx.x * 64;
    const size_t attbase = (size_t)((b * G_ + g) * HKV_ + h) * T_ * T_;

    {
        const float* src = &g_Q[(size_t)(b * T_ + q0) * C_ + hq * D_];
        for (int idx = tid; idx < 1024; idx += 256) {
            int r = idx >> 4, d = (idx & 15) << 2;
            float4 v = *(const float4*)&src[(size_t)r * C_ + d];
            v.x = tf32rn(v.x); v.y = tf32rn(v.y); v.z = tf32rn(v.z); v.w = tf32rn(v.w);
            *(float4*)&Qs[r * PAD + d] = v;
        }
    }

    const float mr0 = g_M[bh * T_ + q0 + row0];
    const float li0 = 1.f / g_L[bh * T_ + q0 + row0];
    const float mr1 = g_M[bh * T_ + q0 + row0 + 8];
    const float li1 = 1.f / g_L[bh * T_ + q0 + row0 + 8];

    float yc[4][4];
#pragma unroll
    for (int nt = 0; nt < 4; nt++)
#pragma unroll
        for (int e = 0; e < 4; e++) yc[nt][e] = 0.f;

    const int diag = q0 >> 6;
    for (int kt = 0; kt < T_ / 64; kt++) {
        const int k0 = kt * 64;
        if (kt > diag) {
            if (write_att) {
                const float4 z = make_float4(0.f, 0.f, 0.f, 0.f);
                for (int idx = tid; idx < 1024; idx += 256) {
                    int r = idx >> 4, cc = (idx & 15) << 2;
                    *(float4*)&att[attbase + (size_t)(q0 + r) * T_ + k0 + cc] = z;
                }
            }
            continue;
        }

        {
            const float* ksrc = &g_K[(size_t)(b * T_ + k0) * KVC_ + h * D_];
            const float* vsrc = &g_V[(size_t)(b * T_ + k0) * KVC_ + h * D_];
            for (int idx = tid; idx < 1024; idx += 256) {
                int r = idx >> 4, d = (idx & 15) << 2;
                float4 kv = *(const float4*)&ksrc[(size_t)r * KVC_ + d];
                float4 vv = *(const float4*)&vsrc[(size_t)r * KVC_ + d];
                kv.x = tf32rn(kv.x); kv.y = tf32rn(kv.y); kv.z = tf32rn(kv.z); kv.w = tf32rn(kv.w);
                vv.x = tf32rn(vv.x); vv.y = tf32rn(vv.y); vv.z = tf32rn(vv.z); vv.w = tf32rn(vv.w);
                *(float4*)&Ks[r * PAD + d] = kv;
                *(float4*)&Vs[r * PAD + d] = vv;
            }
        }
        __syncthreads();

        float c[4][4];
#pragma unroll
        for (int nt = 0; nt < 4; nt++)
#pragma unroll
            for (int e = 0; e < 4; e++) c[nt][e] = 0.f;
#pragma unroll
        for (int ks2 = 0; ks2 < 8; ks2++) {
            const int d0 = ks2 * 8;
            uint32_t a0 = __float_as_uint(Qs[(row0    ) * PAD + d0 + tig]);
            uint32_t a1 = __float_as_uint(Qs[(row0 + 8) * PAD + d0 + tig]);
            uint32_t a2 = __float_as_uint(Qs[(row0    ) * PAD + d0 + tig + 4]);
            uint32_t a3 = __float_as_uint(Qs[(row0 + 8) * PAD + d0 + tig + 4]);
#pragma unroll
            for (int nt = 0; nt < 4; nt++) {
                const int nc = nbase + nt * 8 + gid;
                uint32_t b0 = __float_as_uint(Ks[nc * PAD + d0 + tig]);
                uint32_t b1 = __float_as_uint(Ks[nc * PAD + d0 + tig + 4]);
                mma_tf32(c[nt], a0, a1, a2, a3, b0, b1);
            }
        }

        const bool dm = (kt == diag);
#pragma unroll
        for (int nt = 0; nt < 4; nt++) {
            const int col  = nbase + nt * 8 + 2 * tig;
            const int colg = k0 + col;
            float v00 = c[nt][0] * 0.125f, v01 = c[nt][1] * 0.125f;
            float v10 = c[nt][2] * 0.125f, v11 = c[nt][3] * 0.125f;
            if (dm) {
                if (colg     > q0 + row0    ) v00 = -1e30f;
                if (colg + 1 > q0 + row0    ) v01 = -1e30f;
                if (colg     > q0 + row0 + 8) v10 = -1e30f;
                if (colg + 1 > q0 + row0 + 8) v11 = -1e30f;
            }
            const float p00 = __expf(v00 - mr0) * li0;
            const float p01 = __expf(v01 - mr0) * li0;
            const float p10 = __expf(v10 - mr1) * li1;
            const float p11 = __expf(v11 - mr1) * li1;
            *(float2*)&Ps[(row0    ) * PAD + col] = make_float2(tf32rn(p00), tf32rn(p01));
            *(float2*)&Ps[(row0 + 8) * PAD + col] = make_float2(tf32rn(p10), tf32rn(p11));
            if (write_att) {
                *(float2*)&att[attbase + (size_t)(q0 + row0    ) * T_ + colg] = make_float2(p00, p01);
                *(float2*)&att[attbase + (size_t)(q0 + row0 + 8) * T_ + colg] = make_float2(p10, p11);
            }
        }
        __syncthreads();

#pragma unroll
        for (int ks2 = 0; ks2 < 8; ks2++) {
            const int kc0 = ks2 * 8;
            uint32_t a0 = __float_as_uint(Ps[(row0    ) * PAD + kc0 + tig]);
            uint32_t a1 = __float_as_uint(Ps[(row0 + 8) * PAD + kc0 + tig]);
            uint32_t a2 = __float_as_uint(Ps[(row0    ) * PAD + kc0 + tig + 4]);
            uint32_t a3 = __float_as_uint(Ps[(row0 + 8) * PAD + kc0 + tig + 4]);
#pragma unroll
            for (int nt = 0; nt < 4; nt++) {
                const int dc = nbase + nt * 8 + gid;
                uint32_t b0 = __float_as_uint(Vs[(kc0 + tig    ) * PAD + dc]);
                uint32_t b1 = __float_as_uint(Vs[(kc0 + tig + 4) * PAD + dc]);
                mma_tf32(yc[nt], a0, a1, a2, a3, b0, b1);
            }
        }
        __syncthreads();
    }

#pragma unroll
    for (int nt = 0; nt < 4; nt++) {
        const int col = nbase + nt * 8 + 2 * tig;
        *(float2*)&g_Y[(size_t)(b * T_ + q0 + row0    ) * C_ + hq * D_ + col] =
            make_float2(yc[nt][0], yc[nt][1]);
        *(float2*)&g_Y[(size_t)(b * T_ + q0 + row0 + 8) * C_ + hq * D_ + col] =
            make_float2(yc[nt][2], yc[nt][3]);
    }
}

// ---------------- launch ----------------
#define FIN_SMEM (4 * 64 * PAD * (int)sizeof(float))   // 69,632 B

extern "C" void kernel_launch(void* const* d_in, const int* in_sizes, int n_in,
                              void* d_out, int out_size)
{
    const float* x  = (const float*)d_in[0];
    const float* Wq = (const float*)d_in[1];
    const float* bq = (const float*)d_in[2];
    const float* Wk = (const float*)d_in[3];
    const float* bk = (const float*)d_in[4];
    const float* Wv = (const float*)d_in[5];
    const float* bv = (const float*)d_in[6];
    const float* Wo = (const float*)d_in[7];
    const float* bo = (const float*)d_in[8];

    static float *qp = nullptr, *kp = nullptr, *vp = nullptr, *yp = nullptr;
    static __nv_bfloat16 *wqh, *wql, *wkh, *wkl, *wvh, *wvl, *woh, *wol;
    if (!qp) {
        cudaGetSymbolAddress((void**)&qp,  g_Q);
        cudaGetSymbolAddress((void**)&kp,  g_K);
        cudaGetSymbolAddress((void**)&vp,  g_V);
        cudaGetSymbolAddress((void**)&yp,  g_Y);
        cudaGetSymbolAddress((void**)&wqh, g_Wqh);
        cudaGetSymbolAddress((void**)&wql, g_Wql);
        cudaGetSymbolAddress((void**)&wkh, g_Wkh);
        cudaGetSymbolAddress((void**)&wkl, g_Wkl);
        cudaGetSymbolAddress((void**)&wvh, g_Wvh);
        cudaGetSymbolAddress((void**)&wvl, g_Wvl);
        cudaGetSymbolAddress((void**)&woh, g_Woh);
        cudaGetSymbolAddress((void**)&wol, g_Wol);
        cudaFuncSetAttribute(attn_finalize_mma,
                             cudaFuncAttributeMaxDynamicSharedMemorySize, FIN_SMEM);
    }

    const size_t yElems   = (size_t)N_ * C_;
    const size_t attElems = (size_t)B_ * G_ * HKV_ * T_ * T_;
    float* out = (float*)d_out;
    float* yOut;
    float* attOut;
    int    writeAtt;
    size_t osz = (size_t)out_size;
    if (osz >= yElems + attElems)      { yOut = out; attOut = out + yElems; writeAtt = 1; }
    else if (osz == attElems)          { yOut = qp;  attOut = out;          writeAtt = 1; }
    else                               { yOut = out; attOut = qp;           writeAtt = 0; }

    dim3 blk(256);
    dim3 tb(32, 8);
    transpose_split<<<dim3(C_   / 32, C_ / 32), tb>>>(Wq, wqh, wql, C_, C_);
    transpose_split<<<dim3(KVC_ / 32, C_ / 32), tb>>>(Wk, wkh, wkl, C_, KVC_);
    transpose_split<<<dim3(KVC_ / 32, C_ / 32), tb>>>(Wv, wvh, wvl, C_, KVC_);
    transpose_split<<<dim3(C_   / 32, C_ / 32), tb>>>(Wo, woh, wol, C_, C_);

    gemm_bf16x3<<<dim3(C_   / 128, N_ / 128), blk>>>(x, wqh, wql, bq, qp, N_, C_,   C_);
    gemm_bf16x3<<<dim3(KVC_ / 128, N_ / 128), blk>>>(x, wkh, wkl, bk, kp, N_, KVC_, C_);
    gemm_bf16x3<<<dim3(KVC_ / 128, N_ / 128), blk>>>(x, wvh, wvl, bv, vp, N_, KVC_, C_);

    attn_stats_mma   <<<dim3(T_ / 64, B_ * HQ_), blk>>>();
    attn_finalize_mma<<<dim3(T_ / 64, B_ * HQ_), blk, FIN_SMEM>>>(attOut, writeAtt);

    gemm_bf16x3<<<dim3(C_ / 128, N_ / 128), blk>>>(yp, woh, wol, bo, yOut, N_, C_, C_);
}